// round 9
// baseline (speedup 1.0000x reference)
#include <cuda_runtime.h>
#include <cuda_fp16.h>
#include <cuda_bf16.h>
#include <cstdint>

// Problem constants
#define IN_F    4096
#define OUT_F   11008
#define M_ROWS  4096
#define NGROUPS 32

// Scratch (no cudaMalloc allowed) — both stored in MMA FRAGMENT layout.
// A: [m16_tile (256)][k16_tile (256)][lane (32)][8 halves]  = 32MB
// B: [n8_tile (1376)][k32_chunk (128)][lane (32)][8 halves] = 90MB
__device__ __align__(16) __half g_Af[(size_t)M_ROWS * IN_F];
__device__ __align__(16) __half g_Bf[(size_t)OUT_F * IN_F];
__device__ float  g_scales[NGROUPS * OUT_F];
__device__ int    g_bad_f16;
__device__ int    g_bad_bf16;

// ---------------------------------------------------------------------------
// scales dtype probe (unchanged from passing rounds)
// ---------------------------------------------------------------------------
__global__ void probe_init() { g_bad_f16 = 0; g_bad_bf16 = 0; }

__global__ void probe_kernel(const void* __restrict__ scales) {
    int i = blockIdx.x * blockDim.x + threadIdx.x;
    if (i >= 176128) return;
    float vf = __half2float(((const __half*)scales)[i]);
    if (!(vf >= 0.0f && vf < 1.0f)) atomicExch(&g_bad_f16, 1);
    float vb = __bfloat162float(((const __nv_bfloat16*)scales)[i]);
    if (!(vb >= 0.0f && vb < 1.0f)) atomicExch(&g_bad_bf16, 1);
}

__global__ void cvt_scales(const void* __restrict__ scales) {
    int i = blockIdx.x * blockDim.x + threadIdx.x;
    if (i >= NGROUPS * OUT_F) return;
    float v;
    if (!g_bad_f16)       v = __half2float(((const __half*)scales)[i]);
    else if (!g_bad_bf16) v = __bfloat162float(((const __nv_bfloat16*)scales)[i]);
    else                  v = ((const float*)scales)[i];
    g_scales[i] = v;
}

// ---------------------------------------------------------------------------
// x (fp32) -> A fragments (validated in round 8).
// ---------------------------------------------------------------------------
__global__ __launch_bounds__(256) void cvtA_kernel(const float* __restrict__ x) {
    const int w    = threadIdx.x >> 5;
    const int lane = threadIdx.x & 31;
    const int tile = blockIdx.x * 8 + w;       // 65536 tiles
    const int m16  = tile >> 8;
    const int k16  = tile & 255;
    const int row  = m16 * 16 + (lane >> 2);
    const int col  = k16 * 16 + 2 * (lane & 3);

    const float2* X = reinterpret_cast<const float2*>(x);
    float2 f0 = X[((size_t)row       * IN_F + col)     >> 1];
    float2 f1 = X[((size_t)(row + 8) * IN_F + col)     >> 1];
    float2 f2 = X[((size_t)row       * IN_F + col + 8) >> 1];
    float2 f3 = X[((size_t)(row + 8) * IN_F + col + 8) >> 1];

    __half2 h0 = __floats2half2_rn(f0.x, f0.y);
    __half2 h1 = __floats2half2_rn(f1.x, f1.y);
    __half2 h2 = __floats2half2_rn(f2.x, f2.y);
    __half2 h3 = __floats2half2_rn(f3.x, f3.y);

    uint4 o;
    o.x = *reinterpret_cast<uint32_t*>(&h0);
    o.y = *reinterpret_cast<uint32_t*>(&h1);
    o.z = *reinterpret_cast<uint32_t*>(&h2);
    o.w = *reinterpret_cast<uint32_t*>(&h3);
    reinterpret_cast<uint4*>(g_Af)[(size_t)tile * 32 + lane] = o;
}

// ---------------------------------------------------------------------------
// Dequant -> B fragments (validated in round 8).
// ---------------------------------------------------------------------------
__global__ __launch_bounds__(256) void dequant_kernel(
    const int* __restrict__ qweight, const int* __restrict__ qzeros)
{
    const int w    = threadIdx.x >> 5;
    const int lane = threadIdx.x & 31;
    const int idx  = blockIdx.x * 8 + w;       // (n8, c):  1376*128 total
    const int n8   = idx >> 7;
    const int c    = idx & 127;
    const int n    = n8 * 8 + (lane >> 2);
    const int p    = lane & 3;
    const int g    = c >> 2;                   // group = (c*32)/128

    const int z = (qzeros[g * (OUT_F / 8) + (n >> 3)] >> ((n & 7) * 4)) & 15;
    const __half2 s2  = __half2half2(__float2half(g_scales[g * OUT_F + n]));
    const __half2 mz2 = __half2half2(__float2half((float)(1024 + z)));

    uint32_t o[4];
    #pragma unroll
    for (int i = 0; i < 4; i++) {
        const uint32_t q = (uint32_t)qweight[(size_t)(c * 4 + i) * OUT_F + n];
        const uint32_t v = q >> (8 * p);
        uint32_t t = (v & 0xFu) | ((v << 12) & 0x000F0000u) | 0x64006400u;
        __half2 r = __hmul2(__hsub2(*(__half2*)&t, mz2), s2);
        o[i] = *(uint32_t*)&r;
    }
    uint4 ov = make_uint4(o[0], o[1], o[2], o[3]);
    reinterpret_cast<uint4*>(g_Bf)[((size_t)n8 * 128 + c) * 32 + lane] = ov;
}

// ---------------------------------------------------------------------------
// Hybrid HGEMM: A via 4-stage cp.async smem pipeline (fragment layout ->
// plain LDS.128), B via direct LDG.128 fragments with 1-iter register
// prefetch. CTA 128x128, 4 warps (2m x 2n), warp 64x64, k-step 32.
// ---------------------------------------------------------------------------
constexpr int NIT = IN_F / 32;            // 128 k32 chunks
constexpr int STG = 4;
constexpr int A_STAGE_U4 = 512;           // 8 m16 x 2 k16 x 32 lanes (uint4)

__device__ __forceinline__ uint32_t smem_u32(const void* p) {
    uint32_t a;
    asm("{ .reg .u64 t; cvta.to.shared.u64 t, %1; cvt.u32.u64 %0, t; }"
        : "=r"(a) : "l"(p));
    return a;
}

__global__ __launch_bounds__(128, 2) void gemm_kernel(
    const float* __restrict__ bias, float* __restrict__ out)
{
    __shared__ __align__(16) uint4 As[STG * A_STAGE_U4];   // 32 KB

    const uint32_t sbase = smem_u32(As);
    const int tid  = threadIdx.x;
    const int lane = tid & 31;
    const int warp = tid >> 5;
    const int warp_m = warp & 1;
    const int warp_n = warp >> 1;

    // grid: m fastest -> A (32MB, L2-resident) reused across n-bands
    const int pid_m = blockIdx.x & 31;       // 32
    const int pid_n = blockIdx.x >> 5;       // 86
    const int m_base = pid_m * 128;
    const int n_base = pid_n * 128;

    // A producer source: CTA's 8 m16 tiles
    const uint4* Asrc = reinterpret_cast<const uint4*>(g_Af)
                        + (size_t)(pid_m * 8) * 256 * 32;
    // B fragments: warp's 8 n8 tiles
    const uint4* pB = reinterpret_cast<const uint4*>(g_Bf)
                      + ((size_t)(pid_n * 16 + warp_n * 8)) * 128 * 32 + lane;

    float acc[4][8][4];
    #pragma unroll
    for (int mi = 0; mi < 4; mi++)
        #pragma unroll
        for (int ni = 0; ni < 8; ni++)
            #pragma unroll
            for (int r = 0; r < 4; r++) acc[mi][ni][r] = 0.f;

    // A stage fill: 512 x 16B, 4 per thread. idx = m16_local*64 + j*32 + lane
    auto produceA = [&](int cc) {
        const uint32_t dst = sbase + (cc % STG) * (A_STAGE_U4 * 16);
        #pragma unroll
        for (int i = 0; i < 4; i++) {
            int idx = tid + i * 128;                       // 0..511
            int m16l = idx >> 6, j = (idx >> 5) & 1, ln = idx & 31;
            const uint4* src = Asrc + ((size_t)m16l * 256 + 2 * cc + j) * 32 + ln;
            asm volatile("cp.async.cg.shared.global [%0], [%1], 16;\n"
                         :: "r"(dst + idx * 16), "l"(src));
        }
        asm volatile("cp.async.commit_group;\n");
    };

    uint4 bv[2][8];
    #pragma unroll
    for (int nt = 0; nt < 8; nt++)
        bv[0][nt] = pB[(size_t)nt * (128 * 32)];           // chunk 0

    produceA(0); produceA(1); produceA(2);

    for (int c = 0; c < NIT; c++) {
        const int cur = c & 1;
        // prefetch B chunk c+1 (clamped; redundant final load is harmless)
        const int cn = (c + 1 < NIT) ? (c + 1) : c;
        #pragma unroll
        for (int nt = 0; nt < 8; nt++)
            bv[cur ^ 1][nt] = pB[(size_t)nt * (128 * 32) + (size_t)cn * 32];

        asm volatile("cp.async.wait_group 2;\n");          // A stage c ready
        __syncthreads();

        const uint32_t st = sbase + (c % STG) * (A_STAGE_U4 * 16);
        #pragma unroll
        for (int ks = 0; ks < 2; ks++) {
            uint4 av[4];
            #pragma unroll
            for (int mi = 0; mi < 4; mi++) {
                uint32_t addr = st +
                    (((warp_m * 4 + mi) * 64) + ks * 32 + lane) * 16;
                asm volatile("ld.shared.v4.u32 {%0,%1,%2,%3}, [%4];"
                    : "=r"(av[mi].x), "=r"(av[mi].y),
                      "=r"(av[mi].z), "=r"(av[mi].w)
                    : "r"(addr));
            }
            #pragma unroll
            for (int mi = 0; mi < 4; mi++) {
                #pragma unroll
                for (int nt = 0; nt < 8; nt++) {
                    uint32_t b0 = ks ? bv[cur][nt].z : bv[cur][nt].x;
                    uint32_t b1 = ks ? bv[cur][nt].w : bv[cur][nt].y;
                    asm volatile(
                        "mma.sync.aligned.m16n8k16.row.col.f32.f16.f16.f32 "
                        "{%0,%1,%2,%3}, {%4,%5,%6,%7}, {%8,%9}, {%0,%1,%2,%3};"
                        : "+f"(acc[mi][nt][0]), "+f"(acc[mi][nt][1]),
                          "+f"(acc[mi][nt][2]), "+f"(acc[mi][nt][3])
                        : "r"(av[mi].x), "r"(av[mi].y),
                          "r"(av[mi].z), "r"(av[mi].w),
                          "r"(b0), "r"(b1));
                }
            }
        }

        if (c + 3 < NIT) produceA(c + 3);
        else asm volatile("cp.async.commit_group;\n");     // uniform group count
    }

    // epilogue (same frag->gmem mapping as validated rounds)
    #pragma unroll
    for (int mi = 0; mi < 4; mi++) {
        int row0 = m_base + warp_m * 64 + mi * 16 + (lane >> 2);
        #pragma unroll
        for (int ni = 0; ni < 8; ni++) {
            int col = n_base + warp_n * 64 + ni * 8 + ((lane & 3) << 1);
            float b0 = bias[col], b1 = bias[col + 1];
            float2 v0 = make_float2(acc[mi][ni][0] + b0, acc[mi][ni][1] + b1);
            float2 v1 = make_float2(acc[mi][ni][2] + b0, acc[mi][ni][3] + b1);
            *reinterpret_cast<float2*>(out + (size_t)row0 * OUT_F + col)       = v0;
            *reinterpret_cast<float2*>(out + (size_t)(row0 + 8) * OUT_F + col) = v1;
        }
    }
}

// ---------------------------------------------------------------------------
extern "C" void kernel_launch(void* const* d_in, const int* in_sizes, int n_in,
                              void* d_out, int out_size)
{
    const void *p_x = nullptr, *p_qw = nullptr, *p_qz = nullptr,
               *p_sc = nullptr, *p_b = nullptr;
    for (int i = 0; i < n_in; i++) {
        switch (in_sizes[i]) {
            case M_ROWS * IN_F:        p_x  = d_in[i]; break;
            case (IN_F / 8) * OUT_F:   p_qw = d_in[i]; break;
            case NGROUPS * (OUT_F/8):  p_qz = d_in[i]; break;
            case NGROUPS * OUT_F:      p_sc = d_in[i]; break;
            case OUT_F:                p_b  = d_in[i]; break;
        }
    }

    probe_init<<<1, 1>>>();
    probe_kernel<<<(176128 + 255) / 256, 256>>>(p_sc);
    cvt_scales<<<(NGROUPS * OUT_F + 255) / 256, 256>>>(p_sc);

    // A fragments: 65536 (m16,k16) tiles, 8 per 256-thread block
    cvtA_kernel<<<65536 / 8, 256>>>((const float*)p_x);
    // B fragments: 1376*128 (n8,k32) pairs, 8 per block
    dequant_kernel<<<(1376 * 128) / 8, 256>>>((const int*)p_qw,
                                              (const int*)p_qz);

    // grid: 32 m-tiles x 86 n-tiles, m fastest; static smem only
    gemm_kernel<<<32 * 86, 128>>>((const float*)p_b, (float*)d_out);
}

// round 10
// speedup vs baseline: 1.5643x; 1.5643x over previous
#include <cuda_runtime.h>
#include <cuda_fp16.h>
#include <cuda_bf16.h>
#include <cstdint>

// Problem constants
#define IN_F    4096
#define OUT_F   11008
#define M_ROWS  4096
#define NGROUPS 32

// Scratch (no cudaMalloc allowed)
__device__ __half g_Xh[(size_t)M_ROWS * IN_F];    // fp16 x
__device__ __half g_Wh[(size_t)OUT_F * IN_F];     // fp16 dequant W, [n][k]
__device__ float  g_scales[NGROUPS * OUT_F];
__device__ int    g_bad_f16;
__device__ int    g_bad_bf16;

// ---------------------------------------------------------------------------
// scales dtype probe (unchanged from passing rounds)
// ---------------------------------------------------------------------------
__global__ void probe_init() { g_bad_f16 = 0; g_bad_bf16 = 0; }

__global__ void probe_kernel(const void* __restrict__ scales) {
    int i = blockIdx.x * blockDim.x + threadIdx.x;
    if (i >= 176128) return;
    float vf = __half2float(((const __half*)scales)[i]);
    if (!(vf >= 0.0f && vf < 1.0f)) atomicExch(&g_bad_f16, 1);
    float vb = __bfloat162float(((const __nv_bfloat16*)scales)[i]);
    if (!(vb >= 0.0f && vb < 1.0f)) atomicExch(&g_bad_bf16, 1);
}

__global__ void cvt_scales(const void* __restrict__ scales) {
    int i = blockIdx.x * blockDim.x + threadIdx.x;
    if (i >= NGROUPS * OUT_F) return;
    float v;
    if (!g_bad_f16)       v = __half2float(((const __half*)scales)[i]);
    else if (!g_bad_bf16) v = __bfloat162float(((const __nv_bfloat16*)scales)[i]);
    else                  v = ((const float*)scales)[i];
    g_scales[i] = v;
}

// ---------------------------------------------------------------------------
// x (fp32) -> g_Xh (fp16)
// ---------------------------------------------------------------------------
__global__ void cvt_kernel(const float* __restrict__ x) {
    int idx = (blockIdx.x * blockDim.x + threadIdx.x) * 8;
    float4 f0 = *reinterpret_cast<const float4*>(x + idx);
    float4 f1 = *reinterpret_cast<const float4*>(x + idx + 4);
    __align__(16) __half2 h[4];
    h[0] = __floats2half2_rn(f0.x, f0.y);
    h[1] = __floats2half2_rn(f0.z, f0.w);
    h[2] = __floats2half2_rn(f1.x, f1.y);
    h[3] = __floats2half2_rn(f1.z, f1.w);
    *reinterpret_cast<uint4*>(g_Xh + idx) = *reinterpret_cast<const uint4*>(h);
}

// ---------------------------------------------------------------------------
// Dequant pre-pass (unchanged): qweight int4 -> g_Wh fp16 [n][k]
// ---------------------------------------------------------------------------
__global__ __launch_bounds__(256) void dequant_kernel(
    const int* __restrict__ qweight, const int* __restrict__ qzeros)
{
    const int lane = threadIdx.x;
    const int n    = blockIdx.y * 8 + threadIdx.y;
    const int qrow0 = blockIdx.x * 128 + lane * 4;
    const int g = qrow0 >> 4;

    const int z = (qzeros[g * (OUT_F / 8) + (n >> 3)] >> ((n & 7) * 4)) & 15;
    const __half s  = __float2half(g_scales[g * OUT_F + n]);
    const __half2 s2 = __half2half2(s);
    const __half2 mz2 = __half2half2(__float2half((float)(1024 + z)));

    __half* dst = g_Wh + (size_t)n * IN_F + qrow0 * 8;

    #pragma unroll
    for (int i = 0; i < 4; i++) {
        const uint32_t q = (uint32_t)qweight[(size_t)(qrow0 + i) * OUT_F + n];
        uint32_t t0 = ( q         & 0x000F000Fu) | 0x64006400u;
        uint32_t t1 = ((q >> 4)   & 0x000F000Fu) | 0x64006400u;
        uint32_t t2 = ((q >> 8)   & 0x000F000Fu) | 0x64006400u;
        uint32_t t3 = ((q >> 12)  & 0x000F000Fu) | 0x64006400u;
        __half2 p0 = __hmul2(__hsub2(*(__half2*)&t0, mz2), s2);
        __half2 p1 = __hmul2(__hsub2(*(__half2*)&t1, mz2), s2);
        __half2 p2 = __hmul2(__hsub2(*(__half2*)&t2, mz2), s2);
        __half2 p3 = __hmul2(__hsub2(*(__half2*)&t3, mz2), s2);
        uint32_t u0 = *(uint32_t*)&p0, u1 = *(uint32_t*)&p1;
        uint32_t u2 = *(uint32_t*)&p2, u3 = *(uint32_t*)&p3;
        uint4 o;
        o.x = __byte_perm(u0, u1, 0x5410);
        o.y = __byte_perm(u2, u3, 0x5410);
        o.z = __byte_perm(u0, u1, 0x7632);
        o.w = __byte_perm(u2, u3, 0x7632);
        *reinterpret_cast<uint4*>(dst + i * 8) = o;
    }
}

// ---------------------------------------------------------------------------
// HGEMM (mma.sync): CTA 128x128, 4 warps (2m x 2n), warp tile 64x64,
// BK=32, 5-stage cp.async, 80KB smem -> 2 CTAs/SM. Fragment loads hoisted
// (all 16 ldmatrix before the 64 mma) for LDS/HMMA overlap.
// ---------------------------------------------------------------------------
constexpr int BM  = 128;
constexpr int BN  = 128;
constexpr int BK  = 32;
constexpr int STG = 5;
constexpr int NIT = IN_F / BK;            // 128
constexpr int A_BYTES = BM * BK * 2;      // 8KB
constexpr int B_BYTES = BN * BK * 2;      // 8KB
constexpr int STAGE_BYTES = A_BYTES + B_BYTES;          // 16KB
constexpr int GEMM_SMEM = STG * STAGE_BYTES;            // 80KB

__device__ __forceinline__ uint32_t smem_u32(const void* p) {
    uint32_t a;
    asm("{ .reg .u64 t; cvta.to.shared.u64 t, %1; cvt.u32.u64 %0, t; }"
        : "=r"(a) : "l"(p));
    return a;
}
// byte offset of (row, 8-half chunk ch) within a tile, 64B rows, XOR swizzle
__device__ __forceinline__ uint32_t sw_byte(int row, int ch) {
    return (uint32_t)(row * 64 + ((ch ^ ((row >> 1) & 3)) << 4));
}

__global__ __launch_bounds__(128, 2) void gemm_kernel(
    const float* __restrict__ bias, float* __restrict__ out)
{
    extern __shared__ char smem[];
    const uint32_t sbase = smem_u32(smem);

    const int tid  = threadIdx.x;
    const int lane = tid & 31;
    const int warp = tid >> 5;        // 0..3
    const int warp_m = warp & 1;      // 2 m-warps
    const int warp_n = warp >> 1;     // 2 n-warps

    // grid: m fastest -> A (32MB) stays L2 resident across n-bands
    const int pid_m = blockIdx.x & 31;       // 32
    const int pid_n = blockIdx.x >> 5;       // 86
    const int m_base = pid_m * BM;
    const int n_base = pid_n * BN;

    float acc[4][8][4];
    #pragma unroll
    for (int mi = 0; mi < 4; mi++)
        #pragma unroll
        for (int ni = 0; ni < 8; ni++)
            #pragma unroll
            for (int r = 0; r < 4; r++) acc[mi][ni][r] = 0.f;

    // producer: 1024 16B copies (A 512, B 512), 8 per thread
    auto produce = [&](int cc) {
        const uint32_t st = sbase + (cc % STG) * STAGE_BYTES;
        const int k0 = cc * BK;
        #pragma unroll
        for (int i = 0; i < 8; i++) {
            int id = tid + i * 128;           // 0..1023
            if (id < 512) {
                int row = id >> 2, ch = id & 3;
                const __half* src = g_Xh + (size_t)(m_base + row) * IN_F + k0 + ch * 8;
                asm volatile("cp.async.cg.shared.global [%0], [%1], 16;\n"
                             :: "r"(st + sw_byte(row, ch)), "l"(src));
            } else {
                int idb = id - 512;
                int row = idb >> 2, ch = idb & 3;
                const __half* src = g_Wh + (size_t)(n_base + row) * IN_F + k0 + ch * 8;
                asm volatile("cp.async.cg.shared.global [%0], [%1], 16;\n"
                             :: "r"(st + A_BYTES + sw_byte(row, ch)), "l"(src));
            }
        }
        asm volatile("cp.async.commit_group;\n");
    };

    auto compute = [&](int cc) {
        const uint32_t st = sbase + (cc % STG) * STAGE_BYTES;
        uint32_t a[2][4][4], b[2][8][2];
        // hoisted fragment loads: both ks halves, A then B (16 ldmatrix)
        #pragma unroll
        for (int ks = 0; ks < 2; ks++) {
            const int kc = ks * 2;
            #pragma unroll
            for (int mi = 0; mi < 4; mi++) {
                int row = warp_m * 64 + mi * 16 + (lane & 15);
                int ch  = kc + (lane >> 4);
                uint32_t addr = st + sw_byte(row, ch);
                asm volatile(
                    "ldmatrix.sync.aligned.m8n8.x4.shared.b16 {%0,%1,%2,%3}, [%4];"
                    : "=r"(a[ks][mi][0]), "=r"(a[ks][mi][1]),
                      "=r"(a[ks][mi][2]), "=r"(a[ks][mi][3])
                    : "r"(addr));
            }
            #pragma unroll
            for (int nt = 0; nt < 4; nt++) {  // x4 covers two n8 tiles
                int row = warp_n * 64 + nt * 16 + ((lane >> 4) << 3) + (lane & 7);
                int ch  = kc + ((lane >> 3) & 1);
                uint32_t addr = st + A_BYTES + sw_byte(row, ch);
                asm volatile(
                    "ldmatrix.sync.aligned.m8n8.x4.shared.b16 {%0,%1,%2,%3}, [%4];"
                    : "=r"(b[ks][2*nt][0]), "=r"(b[ks][2*nt][1]),
                      "=r"(b[ks][2*nt+1][0]), "=r"(b[ks][2*nt+1][1])
                    : "r"(addr));
            }
        }
        #pragma unroll
        for (int ks = 0; ks < 2; ks++)
            #pragma unroll
            for (int mi = 0; mi < 4; mi++)
                #pragma unroll
                for (int ni = 0; ni < 8; ni++)
                    asm volatile(
                        "mma.sync.aligned.m16n8k16.row.col.f32.f16.f16.f32 "
                        "{%0,%1,%2,%3}, {%4,%5,%6,%7}, {%8,%9}, {%0,%1,%2,%3};"
                        : "+f"(acc[ks ? 3 - mi : mi][ni][0]),
                          "+f"(acc[ks ? 3 - mi : mi][ni][1]),
                          "+f"(acc[ks ? 3 - mi : mi][ni][2]),
                          "+f"(acc[ks ? 3 - mi : mi][ni][3])
                        : "r"(a[ks][ks ? 3 - mi : mi][0]), "r"(a[ks][ks ? 3 - mi : mi][1]),
                          "r"(a[ks][ks ? 3 - mi : mi][2]), "r"(a[ks][ks ? 3 - mi : mi][3]),
                          "r"(b[ks][ni][0]), "r"(b[ks][ni][1]));
    };

    // prologue: stages 0..3 in flight
    produce(0);
    produce(1);
    produce(2);
    produce(3);

    for (int c = 0; c < NIT; c++) {
        asm volatile("cp.async.wait_group 3;\n");        // group c complete
        __syncthreads();                                 // compute(c-1) done
        if (c + 4 < NIT) produce(c + 4);
        else asm volatile("cp.async.commit_group;\n");   // uniform group count
        compute(c);
    }

    // epilogue
    #pragma unroll
    for (int mi = 0; mi < 4; mi++) {
        int row0 = m_base + warp_m * 64 + mi * 16 + (lane >> 2);
        #pragma unroll
        for (int ni = 0; ni < 8; ni++) {
            int col = n_base + warp_n * 64 + ni * 8 + ((lane & 3) << 1);
            float b0 = bias[col], b1 = bias[col + 1];
            float2 v0 = make_float2(acc[mi][ni][0] + b0, acc[mi][ni][1] + b1);
            float2 v1 = make_float2(acc[mi][ni][2] + b0, acc[mi][ni][3] + b1);
            *reinterpret_cast<float2*>(out + (size_t)row0 * OUT_F + col)       = v0;
            *reinterpret_cast<float2*>(out + (size_t)(row0 + 8) * OUT_F + col) = v1;
        }
    }
}

// ---------------------------------------------------------------------------
extern "C" void kernel_launch(void* const* d_in, const int* in_sizes, int n_in,
                              void* d_out, int out_size)
{
    const void *p_x = nullptr, *p_qw = nullptr, *p_qz = nullptr,
               *p_sc = nullptr, *p_b = nullptr;
    for (int i = 0; i < n_in; i++) {
        switch (in_sizes[i]) {
            case M_ROWS * IN_F:        p_x  = d_in[i]; break;
            case (IN_F / 8) * OUT_F:   p_qw = d_in[i]; break;
            case NGROUPS * (OUT_F/8):  p_qz = d_in[i]; break;
            case NGROUPS * OUT_F:      p_sc = d_in[i]; break;
            case OUT_F:                p_b  = d_in[i]; break;
        }
    }

    probe_init<<<1, 1>>>();
    probe_kernel<<<(176128 + 255) / 256, 256>>>(p_sc);
    cvt_scales<<<(NGROUPS * OUT_F + 255) / 256, 256>>>(p_sc);
    cvt_kernel<<<(M_ROWS * IN_F) / (256 * 8), 256>>>((const float*)p_x);
    dequant_kernel<<<dim3(4, OUT_F / 8), dim3(32, 8)>>>((const int*)p_qw,
                                                        (const int*)p_qz);

    // Not stream-ordered; safe and deterministic on every call (incl. capture).
    cudaFuncSetAttribute(gemm_kernel,
                         cudaFuncAttributeMaxDynamicSharedMemorySize, GEMM_SMEM);

    // grid: 32 m-tiles x 86 n-tiles, m fastest
    gemm_kernel<<<32 * 86, 128, GEMM_SMEM>>>((const float*)p_b, (float*)d_out);
}

// round 12
// speedup vs baseline: 1.6174x; 1.0339x over previous
#include <cuda_runtime.h>
#include <cuda_fp16.h>
#include <cuda_bf16.h>
#include <cstdint>

// Problem constants
#define IN_F    4096
#define OUT_F   11008
#define M_ROWS  4096
#define NGROUPS 32

// Scratch (no cudaMalloc allowed)
__device__ __half g_Xh[(size_t)M_ROWS * IN_F];    // fp16 x
__device__ __half g_Wh[(size_t)OUT_F * IN_F];     // fp16 dequant W, [n][k]
__device__ float  g_scales[NGROUPS * OUT_F];
__device__ int    g_bad_f16;
__device__ int    g_bad_bf16;

// ---------------------------------------------------------------------------
// scales dtype probe (unchanged from passing rounds)
// ---------------------------------------------------------------------------
__global__ void probe_init() { g_bad_f16 = 0; g_bad_bf16 = 0; }

__global__ void probe_kernel(const void* __restrict__ scales) {
    int i = blockIdx.x * blockDim.x + threadIdx.x;
    if (i >= 176128) return;
    float vf = __half2float(((const __half*)scales)[i]);
    if (!(vf >= 0.0f && vf < 1.0f)) atomicExch(&g_bad_f16, 1);
    float vb = __bfloat162float(((const __nv_bfloat16*)scales)[i]);
    if (!(vb >= 0.0f && vb < 1.0f)) atomicExch(&g_bad_bf16, 1);
}

__global__ void cvt_scales(const void* __restrict__ scales) {
    int i = blockIdx.x * blockDim.x + threadIdx.x;
    if (i >= NGROUPS * OUT_F) return;
    float v;
    if (!g_bad_f16)       v = __half2float(((const __half*)scales)[i]);
    else if (!g_bad_bf16) v = __bfloat162float(((const __nv_bfloat16*)scales)[i]);
    else                  v = ((const float*)scales)[i];
    g_scales[i] = v;
}

// ---------------------------------------------------------------------------
// x (fp32) -> g_Xh (fp16)
// ---------------------------------------------------------------------------
__global__ void cvt_kernel(const float* __restrict__ x) {
    int idx = (blockIdx.x * blockDim.x + threadIdx.x) * 8;
    float4 f0 = *reinterpret_cast<const float4*>(x + idx);
    float4 f1 = *reinterpret_cast<const float4*>(x + idx + 4);
    __align__(16) __half2 h[4];
    h[0] = __floats2half2_rn(f0.x, f0.y);
    h[1] = __floats2half2_rn(f0.z, f0.w);
    h[2] = __floats2half2_rn(f1.x, f1.y);
    h[3] = __floats2half2_rn(f1.z, f1.w);
    *reinterpret_cast<uint4*>(g_Xh + idx) = *reinterpret_cast<const uint4*>(h);
}

// ---------------------------------------------------------------------------
// Dequant pre-pass (unchanged): qweight int4 -> g_Wh fp16 [n][k]
// ---------------------------------------------------------------------------
__global__ __launch_bounds__(256) void dequant_kernel(
    const int* __restrict__ qweight, const int* __restrict__ qzeros)
{
    const int lane = threadIdx.x;
    const int n    = blockIdx.y * 8 + threadIdx.y;
    const int qrow0 = blockIdx.x * 128 + lane * 4;
    const int g = qrow0 >> 4;

    const int z = (qzeros[g * (OUT_F / 8) + (n >> 3)] >> ((n & 7) * 4)) & 15;
    const __half s  = __float2half(g_scales[g * OUT_F + n]);
    const __half2 s2 = __half2half2(s);
    const __half2 mz2 = __half2half2(__float2half((float)(1024 + z)));

    __half* dst = g_Wh + (size_t)n * IN_F + qrow0 * 8;

    #pragma unroll
    for (int i = 0; i < 4; i++) {
        const uint32_t q = (uint32_t)qweight[(size_t)(qrow0 + i) * OUT_F + n];
        uint32_t t0 = ( q         & 0x000F000Fu) | 0x64006400u;
        uint32_t t1 = ((q >> 4)   & 0x000F000Fu) | 0x64006400u;
        uint32_t t2 = ((q >> 8)   & 0x000F000Fu) | 0x64006400u;
        uint32_t t3 = ((q >> 12)  & 0x000F000Fu) | 0x64006400u;
        __half2 p0 = __hmul2(__hsub2(*(__half2*)&t0, mz2), s2);
        __half2 p1 = __hmul2(__hsub2(*(__half2*)&t1, mz2), s2);
        __half2 p2 = __hmul2(__hsub2(*(__half2*)&t2, mz2), s2);
        __half2 p3 = __hmul2(__hsub2(*(__half2*)&t3, mz2), s2);
        uint32_t u0 = *(uint32_t*)&p0, u1 = *(uint32_t*)&p1;
        uint32_t u2 = *(uint32_t*)&p2, u3 = *(uint32_t*)&p3;
        uint4 o;
        o.x = __byte_perm(u0, u1, 0x5410);
        o.y = __byte_perm(u2, u3, 0x5410);
        o.z = __byte_perm(u0, u1, 0x7632);
        o.w = __byte_perm(u2, u3, 0x7632);
        *reinterpret_cast<uint4*>(dst + i * 8) = o;
    }
}

// ---------------------------------------------------------------------------
// HGEMM (mma.sync): CTA 128x128, 4 warps (2m x 2n), warp tile 64x64,
// BK=64 (half the barrier count vs BK=32), 3-stage cp.async, 96KB smem
// -> 2 CTAs/SM. Rows are 128B, canonical SW128 swizzle (ch ^= row&7).
// Pipeline: produce(c+2) BEFORE compute(c) overwrites stage (c-1) — safe
// behind the __syncthreads; 2 groups in flight.
// ---------------------------------------------------------------------------
constexpr int BM  = 128;
constexpr int BN  = 128;
constexpr int BK  = 64;                   // halves
constexpr int STG = 3;
constexpr int NIT = IN_F / BK;            // 64
constexpr int A_BYTES = BM * BK * 2;      // 16KB
constexpr int B_BYTES = BN * BK * 2;      // 16KB
constexpr int STAGE_BYTES = A_BYTES + B_BYTES;          // 32KB
constexpr int GEMM_SMEM = STG * STAGE_BYTES;            // 96KB

__device__ __forceinline__ uint32_t smem_u32(const void* p) {
    uint32_t a;
    asm("{ .reg .u64 t; cvta.to.shared.u64 t, %1; cvt.u32.u64 %0, t; }"
        : "=r"(a) : "l"(p));
    return a;
}
// byte offset of (row, 16B chunk ch in 0..7) within a tile: 128B rows, SW128
__device__ __forceinline__ uint32_t sw_byte(int row, int ch) {
    return (uint32_t)((row << 7) + ((ch ^ (row & 7)) << 4));
}

__global__ __launch_bounds__(128, 2) void gemm_kernel(
    const float* __restrict__ bias, float* __restrict__ out)
{
    extern __shared__ char smem[];
    const uint32_t sbase = smem_u32(smem);

    const int tid  = threadIdx.x;
    const int lane = tid & 31;
    const int warp = tid >> 5;        // 0..3
    const int warp_m = warp & 1;      // 2 m-warps
    const int warp_n = warp >> 1;     // 2 n-warps

    // grid: m fastest -> A (32MB) stays L2 resident across n-bands
    const int pid_m = blockIdx.x & 31;       // 32
    const int pid_n = blockIdx.x >> 5;       // 86
    const int m_base = pid_m * BM;
    const int n_base = pid_n * BN;

    float acc[4][8][4];
    #pragma unroll
    for (int mi = 0; mi < 4; mi++)
        #pragma unroll
        for (int ni = 0; ni < 8; ni++)
            #pragma unroll
            for (int r = 0; r < 4; r++) acc[mi][ni][r] = 0.f;

    // producer: 2048 16B copies (A 1024, B 1024), 16 per thread
    auto produce = [&](int cc) {
        const uint32_t st = sbase + (cc % STG) * STAGE_BYTES;
        const int k0 = cc * BK;
        #pragma unroll
        for (int i = 0; i < 16; i++) {
            int id = tid + i * 128;           // 0..2047
            if (id < 1024) {
                int row = id >> 3, ch = id & 7;
                const __half* src = g_Xh + (size_t)(m_base + row) * IN_F + k0 + ch * 8;
                asm volatile("cp.async.cg.shared.global [%0], [%1], 16;\n"
                             :: "r"(st + sw_byte(row, ch)), "l"(src));
            } else {
                int idb = id - 1024;
                int row = idb >> 3, ch = idb & 7;
                const __half* src = g_Wh + (size_t)(n_base + row) * IN_F + k0 + ch * 8;
                asm volatile("cp.async.cg.shared.global [%0], [%1], 16;\n"
                             :: "r"(st + A_BYTES + sw_byte(row, ch)), "l"(src));
            }
        }
        asm volatile("cp.async.commit_group;\n");
    };

    auto compute = [&](int cc) {
        const uint32_t st = sbase + (cc % STG) * STAGE_BYTES;
        #pragma unroll
        for (int ks = 0; ks < 4; ks++) {      // 4 k16 sub-steps
            const int kc = ks * 2;
            uint32_t a[4][4], b[8][2];
            #pragma unroll
            for (int mi = 0; mi < 4; mi++) {
                int row = warp_m * 64 + mi * 16 + (lane & 15);
                int ch  = kc + (lane >> 4);
                uint32_t addr = st + sw_byte(row, ch);
                asm volatile(
                    "ldmatrix.sync.aligned.m8n8.x4.shared.b16 {%0,%1,%2,%3}, [%4];"
                    : "=r"(a[mi][0]), "=r"(a[mi][1]), "=r"(a[mi][2]), "=r"(a[mi][3])
                    : "r"(addr));
            }
            #pragma unroll
            for (int nt = 0; nt < 4; nt++) {  // x4 covers two n8 tiles
                int row = warp_n * 64 + nt * 16 + ((lane >> 4) << 3) + (lane & 7);
                int ch  = kc + ((lane >> 3) & 1);
                uint32_t addr = st + A_BYTES + sw_byte(row, ch);
                asm volatile(
                    "ldmatrix.sync.aligned.m8n8.x4.shared.b16 {%0,%1,%2,%3}, [%4];"
                    : "=r"(b[2*nt][0]), "=r"(b[2*nt][1]),
                      "=r"(b[2*nt+1][0]), "=r"(b[2*nt+1][1])
                    : "r"(addr));
            }
            #pragma unroll
            for (int mi = 0; mi < 4; mi++)
                #pragma unroll
                for (int ni = 0; ni < 8; ni++)
                    asm volatile(
                        "mma.sync.aligned.m16n8k16.row.col.f32.f16.f16.f32 "
                        "{%0,%1,%2,%3}, {%4,%5,%6,%7}, {%8,%9}, {%0,%1,%2,%3};"
                        : "+f"(acc[mi][ni][0]), "+f"(acc[mi][ni][1]),
                          "+f"(acc[mi][ni][2]), "+f"(acc[mi][ni][3])
                        : "r"(a[mi][0]), "r"(a[mi][1]), "r"(a[mi][2]), "r"(a[mi][3]),
                          "r"(b[ni][0]), "r"(b[ni][1]));
        }
    };

    // prologue: stages 0,1 in flight
    produce(0);
    produce(1);

    for (int c = 0; c < NIT; c++) {
        asm volatile("cp.async.wait_group 1;\n");        // group c complete
        __syncthreads();                                 // compute(c-1) done
        if (c + 2 < NIT) produce(c + 2);                 // stage (c+2)%3 == (c-1)%3: safe
        else asm volatile("cp.async.commit_group;\n");   // uniform group count
        compute(c);
    }

    // epilogue
    #pragma unroll
    for (int mi = 0; mi < 4; mi++) {
        int row0 = m_base + warp_m * 64 + mi * 16 + (lane >> 2);
        #pragma unroll
        for (int ni = 0; ni < 8; ni++) {
            int col = n_base + warp_n * 64 + ni * 8 + ((lane & 3) << 1);
            float b0 = bias[col], b1 = bias[col + 1];
            float2 v0 = make_float2(acc[mi][ni][0] + b0, acc[mi][ni][1] + b1);
            float2 v1 = make_float2(acc[mi][ni][2] + b0, acc[mi][ni][3] + b1);
            *reinterpret_cast<float2*>(out + (size_t)row0 * OUT_F + col)       = v0;
            *reinterpret_cast<float2*>(out + (size_t)(row0 + 8) * OUT_F + col) = v1;
        }
    }
}

// ---------------------------------------------------------------------------
extern "C" void kernel_launch(void* const* d_in, const int* in_sizes, int n_in,
                              void* d_out, int out_size)
{
    const void *p_x = nullptr, *p_qw = nullptr, *p_qz = nullptr,
               *p_sc = nullptr, *p_b = nullptr;
    for (int i = 0; i < n_in; i++) {
        switch (in_sizes[i]) {
            case M_ROWS * IN_F:        p_x  = d_in[i]; break;
            case (IN_F / 8) * OUT_F:   p_qw = d_in[i]; break;
            case NGROUPS * (OUT_F/8):  p_qz = d_in[i]; break;
            case NGROUPS * OUT_F:      p_sc = d_in[i]; break;
            case OUT_F:                p_b  = d_in[i]; break;
        }
    }

    probe_init<<<1, 1>>>();
    probe_kernel<<<(176128 + 255) / 256, 256>>>(p_sc);
    cvt_scales<<<(NGROUPS * OUT_F + 255) / 256, 256>>>(p_sc);
    cvt_kernel<<<(M_ROWS * IN_F) / (256 * 8), 256>>>((const float*)p_x);
    dequant_kernel<<<dim3(4, OUT_F / 8), dim3(32, 8)>>>((const int*)p_qw,
                                                        (const int*)p_qz);

    // Not stream-ordered; safe and deterministic on every call (incl. capture).
    cudaFuncSetAttribute(gemm_kernel,
                         cudaFuncAttributeMaxDynamicSharedMemorySize, GEMM_SMEM);

    // grid: 32 m-tiles x 86 n-tiles, m fastest
    gemm_kernel<<<32 * 86, 128, GEMM_SMEM>>>((const float*)p_b, (float*)d_out);
}

// round 13
// speedup vs baseline: 1.6207x; 1.0020x over previous
#include <cuda_runtime.h>
#include <cuda_fp16.h>
#include <cuda_bf16.h>
#include <cstdint>

// Problem constants
#define IN_F    4096
#define OUT_F   11008
#define M_ROWS  4096
#define NGROUPS 32

// Scratch (no cudaMalloc allowed)
__device__ __half g_Xh[(size_t)M_ROWS * IN_F];    // fp16 x
__device__ __half g_Wh[(size_t)OUT_F * IN_F];     // fp16 dequant W, [n][k]
__device__ float  g_scales[NGROUPS * OUT_F];
__device__ int    g_bad_f16;
__device__ int    g_bad_bf16;

// ---------------------------------------------------------------------------
// scales dtype probe (unchanged from passing rounds)
// ---------------------------------------------------------------------------
__global__ void probe_init() { g_bad_f16 = 0; g_bad_bf16 = 0; }

__global__ void probe_kernel(const void* __restrict__ scales) {
    int i = blockIdx.x * blockDim.x + threadIdx.x;
    if (i >= 176128) return;
    float vf = __half2float(((const __half*)scales)[i]);
    if (!(vf >= 0.0f && vf < 1.0f)) atomicExch(&g_bad_f16, 1);
    float vb = __bfloat162float(((const __nv_bfloat16*)scales)[i]);
    if (!(vb >= 0.0f && vb < 1.0f)) atomicExch(&g_bad_bf16, 1);
}

__global__ void cvt_scales(const void* __restrict__ scales) {
    int i = blockIdx.x * blockDim.x + threadIdx.x;
    if (i >= NGROUPS * OUT_F) return;
    float v;
    if (!g_bad_f16)       v = __half2float(((const __half*)scales)[i]);
    else if (!g_bad_bf16) v = __bfloat162float(((const __nv_bfloat16*)scales)[i]);
    else                  v = ((const float*)scales)[i];
    g_scales[i] = v;
}

// ---------------------------------------------------------------------------
// Fused pre-pass: blocks [0, 8192) convert x -> g_Xh (fp16);
// blocks [8192, 13696) dequant qweight -> g_Wh. Both paths byte-identical
// to the previously validated kernels; fusing overlaps their DRAM streams.
// 256 threads per block.
// ---------------------------------------------------------------------------
__global__ __launch_bounds__(256) void prep_kernel(
    const float* __restrict__ x,
    const int* __restrict__ qweight, const int* __restrict__ qzeros)
{
    const int bid = blockIdx.x;
    if (bid < 8192) {
        // ---- cvt path: 8 fp32 -> 8 fp16 per thread ----
        int idx = (bid * 256 + threadIdx.x) * 8;
        float4 f0 = *reinterpret_cast<const float4*>(x + idx);
        float4 f1 = *reinterpret_cast<const float4*>(x + idx + 4);
        __align__(16) __half2 h[4];
        h[0] = __floats2half2_rn(f0.x, f0.y);
        h[1] = __floats2half2_rn(f0.z, f0.w);
        h[2] = __floats2half2_rn(f1.x, f1.y);
        h[3] = __floats2half2_rn(f1.z, f1.w);
        *reinterpret_cast<uint4*>(g_Xh + idx) = *reinterpret_cast<const uint4*>(h);
    } else {
        // ---- dequant path: same mapping as validated dequant_kernel ----
        const int r    = bid - 8192;          // 0..5503
        const int bx   = r & 3;               // qrow block (was blockIdx.x)
        const int by   = r >> 2;              // n block (was blockIdx.y)
        const int lane = threadIdx.x & 31;
        const int ty   = threadIdx.x >> 5;    // 0..7 (was threadIdx.y)
        const int n    = by * 8 + ty;
        const int qrow0 = bx * 128 + lane * 4;
        const int g = qrow0 >> 4;

        const int z = (qzeros[g * (OUT_F / 8) + (n >> 3)] >> ((n & 7) * 4)) & 15;
        const __half s  = __float2half(g_scales[g * OUT_F + n]);
        const __half2 s2 = __half2half2(s);
        const __half2 mz2 = __half2half2(__float2half((float)(1024 + z)));

        __half* dst = g_Wh + (size_t)n * IN_F + qrow0 * 8;

        #pragma unroll
        for (int i = 0; i < 4; i++) {
            const uint32_t q = (uint32_t)qweight[(size_t)(qrow0 + i) * OUT_F + n];
            uint32_t t0 = ( q         & 0x000F000Fu) | 0x64006400u;
            uint32_t t1 = ((q >> 4)   & 0x000F000Fu) | 0x64006400u;
            uint32_t t2 = ((q >> 8)   & 0x000F000Fu) | 0x64006400u;
            uint32_t t3 = ((q >> 12)  & 0x000F000Fu) | 0x64006400u;
            __half2 p0 = __hmul2(__hsub2(*(__half2*)&t0, mz2), s2);
            __half2 p1 = __hmul2(__hsub2(*(__half2*)&t1, mz2), s2);
            __half2 p2 = __hmul2(__hsub2(*(__half2*)&t2, mz2), s2);
            __half2 p3 = __hmul2(__hsub2(*(__half2*)&t3, mz2), s2);
            uint32_t u0 = *(uint32_t*)&p0, u1 = *(uint32_t*)&p1;
            uint32_t u2 = *(uint32_t*)&p2, u3 = *(uint32_t*)&p3;
            uint4 o;
            o.x = __byte_perm(u0, u1, 0x5410);
            o.y = __byte_perm(u2, u3, 0x5410);
            o.z = __byte_perm(u0, u1, 0x7632);
            o.w = __byte_perm(u2, u3, 0x7632);
            *reinterpret_cast<uint4*>(dst + i * 8) = o;
        }
    }
}

// ---------------------------------------------------------------------------
// HGEMM (mma.sync) — EXACT round-12 best kernel. CTA 128x128, 4 warps
// (2m x 2n), warp tile 64x64, BK=64, 3-stage cp.async, 96KB smem ->
// 2 CTAs/SM. 128B rows, canonical SW128 swizzle (ch ^= row&7).
// ---------------------------------------------------------------------------
constexpr int BM  = 128;
constexpr int BN  = 128;
constexpr int BK  = 64;                   // halves
constexpr int STG = 3;
constexpr int NIT = IN_F / BK;            // 64
constexpr int A_BYTES = BM * BK * 2;      // 16KB
constexpr int B_BYTES = BN * BK * 2;      // 16KB
constexpr int STAGE_BYTES = A_BYTES + B_BYTES;          // 32KB
constexpr int GEMM_SMEM = STG * STAGE_BYTES;            // 96KB

__device__ __forceinline__ uint32_t smem_u32(const void* p) {
    uint32_t a;
    asm("{ .reg .u64 t; cvta.to.shared.u64 t, %1; cvt.u32.u64 %0, t; }"
        : "=r"(a) : "l"(p));
    return a;
}
// byte offset of (row, 16B chunk ch in 0..7) within a tile: 128B rows, SW128
__device__ __forceinline__ uint32_t sw_byte(int row, int ch) {
    return (uint32_t)((row << 7) + ((ch ^ (row & 7)) << 4));
}

__global__ __launch_bounds__(128, 2) void gemm_kernel(
    const float* __restrict__ bias, float* __restrict__ out)
{
    extern __shared__ char smem[];
    const uint32_t sbase = smem_u32(smem);

    const int tid  = threadIdx.x;
    const int lane = tid & 31;
    const int warp = tid >> 5;        // 0..3
    const int warp_m = warp & 1;      // 2 m-warps
    const int warp_n = warp >> 1;     // 2 n-warps

    // grid: m fastest -> A (32MB) stays L2 resident across n-bands
    const int pid_m = blockIdx.x & 31;       // 32
    const int pid_n = blockIdx.x >> 5;       // 86
    const int m_base = pid_m * BM;
    const int n_base = pid_n * BN;

    float acc[4][8][4];
    #pragma unroll
    for (int mi = 0; mi < 4; mi++)
        #pragma unroll
        for (int ni = 0; ni < 8; ni++)
            #pragma unroll
            for (int r = 0; r < 4; r++) acc[mi][ni][r] = 0.f;

    // producer: 2048 16B copies (A 1024, B 1024), 16 per thread
    auto produce = [&](int cc) {
        const uint32_t st = sbase + (cc % STG) * STAGE_BYTES;
        const int k0 = cc * BK;
        #pragma unroll
        for (int i = 0; i < 16; i++) {
            int id = tid + i * 128;           // 0..2047
            if (id < 1024) {
                int row = id >> 3, ch = id & 7;
                const __half* src = g_Xh + (size_t)(m_base + row) * IN_F + k0 + ch * 8;
                asm volatile("cp.async.cg.shared.global [%0], [%1], 16;\n"
                             :: "r"(st + sw_byte(row, ch)), "l"(src));
            } else {
                int idb = id - 1024;
                int row = idb >> 3, ch = idb & 7;
                const __half* src = g_Wh + (size_t)(n_base + row) * IN_F + k0 + ch * 8;
                asm volatile("cp.async.cg.shared.global [%0], [%1], 16;\n"
                             :: "r"(st + A_BYTES + sw_byte(row, ch)), "l"(src));
            }
        }
        asm volatile("cp.async.commit_group;\n");
    };

    auto compute = [&](int cc) {
        const uint32_t st = sbase + (cc % STG) * STAGE_BYTES;
        #pragma unroll
        for (int ks = 0; ks < 4; ks++) {      // 4 k16 sub-steps
            const int kc = ks * 2;
            uint32_t a[4][4], b[8][2];
            #pragma unroll
            for (int mi = 0; mi < 4; mi++) {
                int row = warp_m * 64 + mi * 16 + (lane & 15);
                int ch  = kc + (lane >> 4);
                uint32_t addr = st + sw_byte(row, ch);
                asm volatile(
                    "ldmatrix.sync.aligned.m8n8.x4.shared.b16 {%0,%1,%2,%3}, [%4];"
                    : "=r"(a[mi][0]), "=r"(a[mi][1]), "=r"(a[mi][2]), "=r"(a[mi][3])
                    : "r"(addr));
            }
            #pragma unroll
            for (int nt = 0; nt < 4; nt++) {  // x4 covers two n8 tiles
                int row = warp_n * 64 + nt * 16 + ((lane >> 4) << 3) + (lane & 7);
                int ch  = kc + ((lane >> 3) & 1);
                uint32_t addr = st + A_BYTES + sw_byte(row, ch);
                asm volatile(
                    "ldmatrix.sync.aligned.m8n8.x4.shared.b16 {%0,%1,%2,%3}, [%4];"
                    : "=r"(b[2*nt][0]), "=r"(b[2*nt][1]),
                      "=r"(b[2*nt+1][0]), "=r"(b[2*nt+1][1])
                    : "r"(addr));
            }
            #pragma unroll
            for (int mi = 0; mi < 4; mi++)
                #pragma unroll
                for (int ni = 0; ni < 8; ni++)
                    asm volatile(
                        "mma.sync.aligned.m16n8k16.row.col.f32.f16.f16.f32 "
                        "{%0,%1,%2,%3}, {%4,%5,%6,%7}, {%8,%9}, {%0,%1,%2,%3};"
                        : "+f"(acc[mi][ni][0]), "+f"(acc[mi][ni][1]),
                          "+f"(acc[mi][ni][2]), "+f"(acc[mi][ni][3])
                        : "r"(a[mi][0]), "r"(a[mi][1]), "r"(a[mi][2]), "r"(a[mi][3]),
                          "r"(b[ni][0]), "r"(b[ni][1]));
        }
    };

    // prologue: stages 0,1 in flight
    produce(0);
    produce(1);

    for (int c = 0; c < NIT; c++) {
        asm volatile("cp.async.wait_group 1;\n");        // group c complete
        __syncthreads();                                 // compute(c-1) done
        if (c + 2 < NIT) produce(c + 2);                 // stage (c+2)%3 == (c-1)%3: safe
        else asm volatile("cp.async.commit_group;\n");   // uniform group count
        compute(c);
    }

    // epilogue
    #pragma unroll
    for (int mi = 0; mi < 4; mi++) {
        int row0 = m_base + warp_m * 64 + mi * 16 + (lane >> 2);
        #pragma unroll
        for (int ni = 0; ni < 8; ni++) {
            int col = n_base + warp_n * 64 + ni * 8 + ((lane & 3) << 1);
            float b0 = bias[col], b1 = bias[col + 1];
            float2 v0 = make_float2(acc[mi][ni][0] + b0, acc[mi][ni][1] + b1);
            float2 v1 = make_float2(acc[mi][ni][2] + b0, acc[mi][ni][3] + b1);
            *reinterpret_cast<float2*>(out + (size_t)row0 * OUT_F + col)       = v0;
            *reinterpret_cast<float2*>(out + (size_t)(row0 + 8) * OUT_F + col) = v1;
        }
    }
}

// ---------------------------------------------------------------------------
extern "C" void kernel_launch(void* const* d_in, const int* in_sizes, int n_in,
                              void* d_out, int out_size)
{
    const void *p_x = nullptr, *p_qw = nullptr, *p_qz = nullptr,
               *p_sc = nullptr, *p_b = nullptr;
    for (int i = 0; i < n_in; i++) {
        switch (in_sizes[i]) {
            case M_ROWS * IN_F:        p_x  = d_in[i]; break;
            case (IN_F / 8) * OUT_F:   p_qw = d_in[i]; break;
            case NGROUPS * (OUT_F/8):  p_qz = d_in[i]; break;
            case NGROUPS * OUT_F:      p_sc = d_in[i]; break;
            case OUT_F:                p_b  = d_in[i]; break;
        }
    }

    probe_init<<<1, 1>>>();
    probe_kernel<<<(176128 + 255) / 256, 256>>>(p_sc);
    cvt_scales<<<(NGROUPS * OUT_F + 255) / 256, 256>>>(p_sc);

    // fused pre-pass: 8192 cvt blocks + 5504 dequant blocks
    prep_kernel<<<8192 + 5504, 256>>>((const float*)p_x,
                                      (const int*)p_qw, (const int*)p_qz);

    // Not stream-ordered; safe and deterministic on every call (incl. capture).
    cudaFuncSetAttribute(gemm_kernel,
                         cudaFuncAttributeMaxDynamicSharedMemorySize, GEMM_SMEM);

    // grid: 32 m-tiles x 86 n-tiles, m fastest
    gemm_kernel<<<32 * 86, 128, GEMM_SMEM>>>((const float*)p_b, (float*)d_out);
}

// round 14
// speedup vs baseline: 1.6575x; 1.0227x over previous
#include <cuda_runtime.h>
#include <cuda_fp16.h>
#include <cuda_bf16.h>
#include <cstdint>

// Problem constants
#define IN_F    4096
#define OUT_F   11008
#define M_ROWS  4096
#define NGROUPS 32

// Scratch (no cudaMalloc allowed)
__device__ __half g_Xh[(size_t)M_ROWS * IN_F];    // fp16 x
__device__ __half g_Wh[(size_t)OUT_F * IN_F];     // fp16 dequant W, [n][k]
__device__ float  g_scales[NGROUPS * OUT_F];
__device__ int    g_bad_f16;
__device__ int    g_bad_bf16;

// ---------------------------------------------------------------------------
// scales dtype probe (unchanged from passing rounds)
// ---------------------------------------------------------------------------
__global__ void probe_init() { g_bad_f16 = 0; g_bad_bf16 = 0; }

__global__ void probe_kernel(const void* __restrict__ scales) {
    int i = blockIdx.x * blockDim.x + threadIdx.x;
    if (i >= 176128) return;
    float vf = __half2float(((const __half*)scales)[i]);
    if (!(vf >= 0.0f && vf < 1.0f)) atomicExch(&g_bad_f16, 1);
    float vb = __bfloat162float(((const __nv_bfloat16*)scales)[i]);
    if (!(vb >= 0.0f && vb < 1.0f)) atomicExch(&g_bad_bf16, 1);
}

__global__ void cvt_scales(const void* __restrict__ scales) {
    int i = blockIdx.x * blockDim.x + threadIdx.x;
    if (i >= NGROUPS * OUT_F) return;
    float v;
    if (!g_bad_f16)       v = __half2float(((const __half*)scales)[i]);
    else if (!g_bad_bf16) v = __bfloat162float(((const __nv_bfloat16*)scales)[i]);
    else                  v = ((const float*)scales)[i];
    g_scales[i] = v;
}

// ---------------------------------------------------------------------------
// Fused pre-pass: blocks [0, 8192) convert x -> g_Xh (fp16);
// blocks [8192, 13696) dequant qweight -> g_Wh with COALESCED reads:
// tile = 32 qrows x 32 n; lanes index n (128B-coalesced qweight reads),
// smem transpose, per-warp 512B contiguous writes. Dequant arithmetic
// bit-identical to the validated kernel (same g_Wh bytes).
// ---------------------------------------------------------------------------
__global__ __launch_bounds__(256) void prep_kernel(
    const float* __restrict__ x,
    const int* __restrict__ qweight, const int* __restrict__ qzeros)
{
    __shared__ __align__(16) uint4 ts[32 * 33];   // [qrow_local][n_local], pad 33

    const int bid = blockIdx.x;
    if (bid < 8192) {
        // ---- cvt path: 8 fp32 -> 8 fp16 per thread ----
        int idx = (bid * 256 + threadIdx.x) * 8;
        float4 f0 = *reinterpret_cast<const float4*>(x + idx);
        float4 f1 = *reinterpret_cast<const float4*>(x + idx + 4);
        __align__(16) __half2 h[4];
        h[0] = __floats2half2_rn(f0.x, f0.y);
        h[1] = __floats2half2_rn(f0.z, f0.w);
        h[2] = __floats2half2_rn(f1.x, f1.y);
        h[3] = __floats2half2_rn(f1.z, f1.w);
        *reinterpret_cast<uint4*>(g_Xh + idx) = *reinterpret_cast<const uint4*>(h);
    } else {
        const int r  = bid - 8192;            // 0..5503
        const int bx = r & 15;                // qrow block: 16 x 32 qrows
        const int by = r >> 4;                // n block: 344 x 32 n
        const int tx = threadIdx.x & 31;      // n_local
        const int ty = threadIdx.x >> 5;      // 0..7 (4 qrows each)
        const int n  = by * 32 + tx;
        const int g  = bx * 2 + (ty >> 2);    // group: qrows ty*4..ty*4+3 share it

        const int z = (qzeros[g * (OUT_F / 8) + (n >> 3)] >> ((n & 7) * 4)) & 15;
        const __half2 s2  = __half2half2(__float2half(g_scales[g * OUT_F + n]));
        const __half2 mz2 = __half2half2(__float2half((float)(1024 + z)));

        // Phase 1: coalesced reads (lanes = consecutive n), dequant, stage
        #pragma unroll
        for (int i = 0; i < 4; i++) {
            const int qrl = ty * 4 + i;                       // qrow_local
            const uint32_t q = (uint32_t)qweight[(size_t)(bx * 32 + qrl) * OUT_F + n];
            uint32_t t0 = ( q         & 0x000F000Fu) | 0x64006400u;
            uint32_t t1 = ((q >> 4)   & 0x000F000Fu) | 0x64006400u;
            uint32_t t2 = ((q >> 8)   & 0x000F000Fu) | 0x64006400u;
            uint32_t t3 = ((q >> 12)  & 0x000F000Fu) | 0x64006400u;
            __half2 p0 = __hmul2(__hsub2(*(__half2*)&t0, mz2), s2);
            __half2 p1 = __hmul2(__hsub2(*(__half2*)&t1, mz2), s2);
            __half2 p2 = __hmul2(__hsub2(*(__half2*)&t2, mz2), s2);
            __half2 p3 = __hmul2(__hsub2(*(__half2*)&t3, mz2), s2);
            uint32_t u0 = *(uint32_t*)&p0, u1 = *(uint32_t*)&p1;
            uint32_t u2 = *(uint32_t*)&p2, u3 = *(uint32_t*)&p3;
            uint4 o;
            o.x = __byte_perm(u0, u1, 0x5410);
            o.y = __byte_perm(u2, u3, 0x5410);
            o.z = __byte_perm(u0, u1, 0x7632);
            o.w = __byte_perm(u2, u3, 0x7632);
            ts[qrl * 33 + tx] = o;
        }
        __syncthreads();

        // Phase 2: per-warp contiguous 512B writes. lane = qrow_local,
        // warp ty covers n_local = ty, ty+8, ty+16, ty+24.
        uint4* W = reinterpret_cast<uint4*>(g_Wh);
        #pragma unroll
        for (int j = 0; j < 4; j++) {
            const int nl = ty + j * 8;
            const int ng = by * 32 + nl;
            W[(size_t)ng * (IN_F / 8) + bx * 32 + tx] = ts[tx * 33 + nl];
        }
    }
}

// ---------------------------------------------------------------------------
// HGEMM (mma.sync) — EXACT round-12/13 best kernel. CTA 128x128, 4 warps
// (2m x 2n), warp tile 64x64, BK=64, 3-stage cp.async, 96KB smem ->
// 2 CTAs/SM. 128B rows, canonical SW128 swizzle (ch ^= row&7).
// ---------------------------------------------------------------------------
constexpr int BM  = 128;
constexpr int BN  = 128;
constexpr int BK  = 64;                   // halves
constexpr int STG = 3;
constexpr int NIT = IN_F / BK;            // 64
constexpr int A_BYTES = BM * BK * 2;      // 16KB
constexpr int B_BYTES = BN * BK * 2;      // 16KB
constexpr int STAGE_BYTES = A_BYTES + B_BYTES;          // 32KB
constexpr int GEMM_SMEM = STG * STAGE_BYTES;            // 96KB

__device__ __forceinline__ uint32_t smem_u32(const void* p) {
    uint32_t a;
    asm("{ .reg .u64 t; cvta.to.shared.u64 t, %1; cvt.u32.u64 %0, t; }"
        : "=r"(a) : "l"(p));
    return a;
}
// byte offset of (row, 16B chunk ch in 0..7) within a tile: 128B rows, SW128
__device__ __forceinline__ uint32_t sw_byte(int row, int ch) {
    return (uint32_t)((row << 7) + ((ch ^ (row & 7)) << 4));
}

__global__ __launch_bounds__(128, 2) void gemm_kernel(
    const float* __restrict__ bias, float* __restrict__ out)
{
    extern __shared__ char smem[];
    const uint32_t sbase = smem_u32(smem);

    const int tid  = threadIdx.x;
    const int lane = tid & 31;
    const int warp = tid >> 5;        // 0..3
    const int warp_m = warp & 1;      // 2 m-warps
    const int warp_n = warp >> 1;     // 2 n-warps

    // grid: m fastest -> A (32MB) stays L2 resident across n-bands
    const int pid_m = blockIdx.x & 31;       // 32
    const int pid_n = blockIdx.x >> 5;       // 86
    const int m_base = pid_m * BM;
    const int n_base = pid_n * BN;

    float acc[4][8][4];
    #pragma unroll
    for (int mi = 0; mi < 4; mi++)
        #pragma unroll
        for (int ni = 0; ni < 8; ni++)
            #pragma unroll
            for (int r = 0; r < 4; r++) acc[mi][ni][r] = 0.f;

    // producer: 2048 16B copies (A 1024, B 1024), 16 per thread
    auto produce = [&](int cc) {
        const uint32_t st = sbase + (cc % STG) * STAGE_BYTES;
        const int k0 = cc * BK;
        #pragma unroll
        for (int i = 0; i < 16; i++) {
            int id = tid + i * 128;           // 0..2047
            if (id < 1024) {
                int row = id >> 3, ch = id & 7;
                const __half* src = g_Xh + (size_t)(m_base + row) * IN_F + k0 + ch * 8;
                asm volatile("cp.async.cg.shared.global [%0], [%1], 16;\n"
                             :: "r"(st + sw_byte(row, ch)), "l"(src));
            } else {
                int idb = id - 1024;
                int row = idb >> 3, ch = idb & 7;
                const __half* src = g_Wh + (size_t)(n_base + row) * IN_F + k0 + ch * 8;
                asm volatile("cp.async.cg.shared.global [%0], [%1], 16;\n"
                             :: "r"(st + A_BYTES + sw_byte(row, ch)), "l"(src));
            }
        }
        asm volatile("cp.async.commit_group;\n");
    };

    auto compute = [&](int cc) {
        const uint32_t st = sbase + (cc % STG) * STAGE_BYTES;
        #pragma unroll
        for (int ks = 0; ks < 4; ks++) {      // 4 k16 sub-steps
            const int kc = ks * 2;
            uint32_t a[4][4], b[8][2];
            #pragma unroll
            for (int mi = 0; mi < 4; mi++) {
                int row = warp_m * 64 + mi * 16 + (lane & 15);
                int ch  = kc + (lane >> 4);
                uint32_t addr = st + sw_byte(row, ch);
                asm volatile(
                    "ldmatrix.sync.aligned.m8n8.x4.shared.b16 {%0,%1,%2,%3}, [%4];"
                    : "=r"(a[mi][0]), "=r"(a[mi][1]), "=r"(a[mi][2]), "=r"(a[mi][3])
                    : "r"(addr));
            }
            #pragma unroll
            for (int nt = 0; nt < 4; nt++) {  // x4 covers two n8 tiles
                int row = warp_n * 64 + nt * 16 + ((lane >> 4) << 3) + (lane & 7);
                int ch  = kc + ((lane >> 3) & 1);
                uint32_t addr = st + A_BYTES + sw_byte(row, ch);
                asm volatile(
                    "ldmatrix.sync.aligned.m8n8.x4.shared.b16 {%0,%1,%2,%3}, [%4];"
                    : "=r"(b[2*nt][0]), "=r"(b[2*nt][1]),
                      "=r"(b[2*nt+1][0]), "=r"(b[2*nt+1][1])
                    : "r"(addr));
            }
            #pragma unroll
            for (int mi = 0; mi < 4; mi++)
                #pragma unroll
                for (int ni = 0; ni < 8; ni++)
                    asm volatile(
                        "mma.sync.aligned.m16n8k16.row.col.f32.f16.f16.f32 "
                        "{%0,%1,%2,%3}, {%4,%5,%6,%7}, {%8,%9}, {%0,%1,%2,%3};"
                        : "+f"(acc[mi][ni][0]), "+f"(acc[mi][ni][1]),
                          "+f"(acc[mi][ni][2]), "+f"(acc[mi][ni][3])
                        : "r"(a[mi][0]), "r"(a[mi][1]), "r"(a[mi][2]), "r"(a[mi][3]),
                          "r"(b[ni][0]), "r"(b[ni][1]));
        }
    };

    // prologue: stages 0,1 in flight
    produce(0);
    produce(1);

    for (int c = 0; c < NIT; c++) {
        asm volatile("cp.async.wait_group 1;\n");        // group c complete
        __syncthreads();                                 // compute(c-1) done
        if (c + 2 < NIT) produce(c + 2);                 // stage (c+2)%3 == (c-1)%3: safe
        else asm volatile("cp.async.commit_group;\n");   // uniform group count
        compute(c);
    }

    // epilogue
    #pragma unroll
    for (int mi = 0; mi < 4; mi++) {
        int row0 = m_base + warp_m * 64 + mi * 16 + (lane >> 2);
        #pragma unroll
        for (int ni = 0; ni < 8; ni++) {
            int col = n_base + warp_n * 64 + ni * 8 + ((lane & 3) << 1);
            float b0 = bias[col], b1 = bias[col + 1];
            float2 v0 = make_float2(acc[mi][ni][0] + b0, acc[mi][ni][1] + b1);
            float2 v1 = make_float2(acc[mi][ni][2] + b0, acc[mi][ni][3] + b1);
            *reinterpret_cast<float2*>(out + (size_t)row0 * OUT_F + col)       = v0;
            *reinterpret_cast<float2*>(out + (size_t)(row0 + 8) * OUT_F + col) = v1;
        }
    }
}

// ---------------------------------------------------------------------------
extern "C" void kernel_launch(void* const* d_in, const int* in_sizes, int n_in,
                              void* d_out, int out_size)
{
    const void *p_x = nullptr, *p_qw = nullptr, *p_qz = nullptr,
               *p_sc = nullptr, *p_b = nullptr;
    for (int i = 0; i < n_in; i++) {
        switch (in_sizes[i]) {
            case M_ROWS * IN_F:        p_x  = d_in[i]; break;
            case (IN_F / 8) * OUT_F:   p_qw = d_in[i]; break;
            case NGROUPS * (OUT_F/8):  p_qz = d_in[i]; break;
            case NGROUPS * OUT_F:      p_sc = d_in[i]; break;
            case OUT_F:                p_b  = d_in[i]; break;
        }
    }

    probe_init<<<1, 1>>>();
    probe_kernel<<<(176128 + 255) / 256, 256>>>(p_sc);
    cvt_scales<<<(NGROUPS * OUT_F + 255) / 256, 256>>>(p_sc);

    // fused pre-pass: 8192 cvt blocks + 5504 dequant blocks (16 x 344 tiles)
    prep_kernel<<<8192 + 5504, 256>>>((const float*)p_x,
                                      (const int*)p_qw, (const int*)p_qz);

    // Not stream-ordered; safe and deterministic on every call (incl. capture).
    cudaFuncSetAttribute(gemm_kernel,
                         cudaFuncAttributeMaxDynamicSharedMemorySize, GEMM_SMEM);

    // grid: 32 m-tiles x 86 n-tiles, m fastest
    gemm_kernel<<<32 * 86, 128, GEMM_SMEM>>>((const float*)p_b, (float*)d_out);
}